// round 3
// baseline (speedup 1.0000x reference)
#include <cuda_runtime.h>
#include <cstdint>

#define NG   262144          // graphs
#define NPP  (NG/2)          // graph pairs (2 graphs per warp, packed f32x2)
#define NPG  6               // nodes per graph
#define NN   (NG*NPG)        // nodes
#define FD   13              // input features
#define HD   32              // hidden
#define GD   9               // global features
#define EPG  30              // directed edges per graph (6-clique)
#define BNEPS 1e-5f

typedef unsigned long long u64;

// ---------------- packed f32x2 helpers ----------------
__device__ __forceinline__ u64 pk2(float x, float y) {
    u64 u; asm("mov.b64 %0,{%1,%2};" : "=l"(u) : "f"(x), "f"(y)); return u;
}
__device__ __forceinline__ void up2(u64 u, float& x, float& y) {
    asm("mov.b64 {%0,%1},%2;" : "=f"(x), "=f"(y) : "l"(u));
}
__device__ __forceinline__ u64 fma2_(u64 a, u64 b, u64 c) {
    u64 d; asm("fma.rn.f32x2 %0,%1,%2,%3;" : "=l"(d) : "l"(a), "l"(b), "l"(c)); return d;
}
__device__ __forceinline__ u64 add2_(u64 a, u64 b) {
    u64 d; asm("add.rn.f32x2 %0,%1,%2;" : "=l"(d) : "l"(a), "l"(b)); return d;
}
__device__ __forceinline__ u64 relu2_(u64 a) {
    float x, y; up2(a, x, y);
    return pk2(fmaxf(x, 0.f), fmaxf(y, 0.f));
}

// ---------------- scratch (static device arrays; paired layout [pair][node][feat]{g0,g1}) ----------------
__device__ u64 g_h1[(size_t)NPP * NPG * HD];   // 201 MB
__device__ u64 g_h2[(size_t)NPP * NPG * HD];   // 201 MB
__device__ float g_sum1[HD], g_sq1[HD], g_sum2[HD], g_sq2[HD];
__device__ float g_scale1[HD], g_shift1[HD], g_scale2[HD], g_shift2[HD];

__global__ void k_zero_stats() {
    int i = threadIdx.x;
    if (i < HD) { g_sum1[i] = 0.f; g_sq1[i] = 0.f; g_sum2[i] = 0.f; g_sq2[i] = 0.f; }
}

// lane t<6 computes deg[t] = 1 + sum of incoming weights; all lanes get dv[s]=rsqrt(deg[s]).
__device__ __forceinline__ void dinv6(float we, int lane, float dv[6]) {
    float d = 1.0f;
    int t = lane;
    #pragma unroll
    for (int s = 0; s < 6; s++) {
        int idx = (s * 5 + (t < s ? t : t - 1)) & 31;
        float w = __shfl_sync(0xffffffffu, we, idx);
        if (t < 6 && s != t) d += w;
    }
    float dvt = (t < 6) ? rsqrtf(d) : 0.f;
    #pragma unroll
    for (int s = 0; s < 6; s++) dv[s] = __shfl_sync(0xffffffffu, dvt, s);
}

// build packed normalized adjacency into shared (row stride 8 u64, 16B aligned rows)
__device__ __forceinline__ void buildA2(float e0, float e1, int lane,
                                        const float dv0[6], const float dv1[6], u64* sA2) {
    if (lane < EPG) {
        int s = lane / 5, j = lane - s * 5, t = j + (j >= s);
        sA2[t * 8 + s] = pk2(dv0[t] * e0 * dv0[s], dv1[t] * e1 * dv1[s]);
    }
    if (lane < 6) sA2[lane * 8 + lane] = pk2(dv0[lane] * dv0[lane], dv1[lane] * dv1[lane]);
}

// ---------------- K1: h1_pre = (A @ x) @ W1 + b1 (2 graphs/warp) ; BN1 stats ----------------
__global__ void __launch_bounds__(256) k1(const float* __restrict__ x,
                                          const float* __restrict__ ew,
                                          const float* __restrict__ W1,
                                          const float* __restrict__ b1) {
    __shared__ __align__(16) u64 sbuf[8][224];   // per warp: sx2[0..77], sA2[80..127], sxa2[128..223]
    __shared__ float sred[8][64];
    const int lane = threadIdx.x & 31, w = threadIdx.x >> 5;
    u64* sx2  = sbuf[w];
    u64* sA2  = sbuf[w] + 80;
    u64* sxa2 = sbuf[w] + 128;

    u64 wp[14];
    #pragma unroll
    for (int c = 0; c < FD; c++) { float v = W1[c * HD + lane]; wp[c] = pk2(v, v); }
    wp[13] = 0ull;
    const float b1l = b1[lane];
    const u64 bias2 = pk2(b1l, b1l);

    if (lane < 6) sxa2[lane * 16 + 13] = 0ull;   // pad read by float4 covering c=12,13
    __syncwarp();

    u64 ssum = 0ull, ssq = 0ull;
    const int warpId = (blockIdx.x * blockDim.x + threadIdx.x) >> 5;
    const int nwarps = (gridDim.x * blockDim.x) >> 5;

    for (int p = warpId; p < NPP; p += nwarps) {
        const float* x0 = x + (size_t)p * (2 * NPG * FD);
        #pragma unroll
        for (int r = 0; r < 3; r++) {
            int i = lane + r * 32;
            if (i < NPG * FD) sx2[i] = pk2(x0[i], x0[NPG * FD + i]);
        }
        float e0 = (lane < EPG) ? ew[(size_t)p * (2 * EPG) + lane] : 0.f;
        float e1 = (lane < EPG) ? ew[(size_t)p * (2 * EPG) + EPG + lane] : 0.f;
        float dv0[6], dv1[6];
        dinv6(e0, lane, dv0); dinv6(e1, lane, dv1);
        buildA2(e0, e1, lane, dv0, dv1, sA2);
        __syncwarp();

        // xa2[t][c] = sum_s A2[t][s] * x2[s][c]
        #pragma unroll
        for (int r = 0; r < 3; r++) {
            int i = lane + r * 32;
            if (i < NPG * FD) {
                int t = i / FD, c = i - t * FD;
                u64 v = 0ull;
                const float4* arow = (const float4*)(sA2 + t * 8);
                #pragma unroll
                for (int sh = 0; sh < 3; sh++) {
                    float4 a4 = arow[sh];
                    v = fma2_(pk2(a4.x, a4.y), sx2[(2 * sh) * FD + c], v);
                    v = fma2_(pk2(a4.z, a4.w), sx2[(2 * sh + 1) * FD + c], v);
                }
                sxa2[t * 16 + c] = v;
            }
        }
        __syncwarp();

        u64* outp = g_h1 + (size_t)p * (NPG * HD) + lane;
        #pragma unroll
        for (int t = 0; t < NPG; t++) {
            u64 acc = bias2;
            const float4* rowp = (const float4*)(sxa2 + t * 16);
            #pragma unroll
            for (int cc = 0; cc < 7; cc++) {
                float4 v4 = rowp[cc];
                acc = fma2_(pk2(v4.x, v4.y), wp[2 * cc], acc);
                acc = fma2_(pk2(v4.z, v4.w), wp[2 * cc + 1], acc);
            }
            outp[t * HD] = acc;
            ssum = add2_(ssum, acc);
            ssq  = fma2_(acc, acc, ssq);
        }
        __syncwarp();
    }

    float sa, sb, qa, qb;
    up2(ssum, sa, sb); up2(ssq, qa, qb);
    sred[w][lane] = sa + sb; sred[w][32 + lane] = qa + qb;
    __syncthreads();
    if (threadIdx.x < 64) {
        float tot = 0.f;
        #pragma unroll
        for (int i = 0; i < 8; i++) tot += sred[i][threadIdx.x];
        if (threadIdx.x < 32) atomicAdd(&g_sum1[threadIdx.x], tot);
        else                  atomicAdd(&g_sq1[threadIdx.x - 32], tot);
    }
}

// ---------------- finalize BN params ----------------
__global__ void k_bn(const float* __restrict__ gam, const float* __restrict__ bet, int which) {
    int f = threadIdx.x;
    if (f < HD) {
        float n = (float)NN;
        float s  = which ? g_sum2[f] : g_sum1[f];
        float sq = which ? g_sq2[f]  : g_sq1[f];
        float mean = s / n;
        float var = sq / n - mean * mean;
        if (var < 0.f) var = 0.f;
        float sc = gam[f] * rsqrtf(var + BNEPS);
        float sh = bet[f] - mean * sc;
        if (which) { g_scale2[f] = sc; g_shift2[f] = sh; }
        else       { g_scale1[f] = sc; g_shift1[f] = sh; }
    }
}

// ---------------- K3: h1=relu(bn1(h1_pre)); h2_pre=(A@h1)@W2+b2 (2 graphs/warp) ; BN2 stats ----------------
__global__ void __launch_bounds__(256) k3(const float* __restrict__ ew,
                                          const float* __restrict__ W2,
                                          const float* __restrict__ b2) {
    __shared__ __align__(16) u64 sbuf[8][240];   // per warp: sA2[0..47], sha2[48..239]
    __shared__ float sred[8][64];
    const int lane = threadIdx.x & 31, w = threadIdx.x >> 5;
    u64* sA2  = sbuf[w];
    u64* sha2 = sbuf[w] + 48;

    u64 wp[HD];
    #pragma unroll
    for (int c = 0; c < HD; c++) { float v = W2[c * HD + lane]; wp[c] = pk2(v, v); }
    const float b2l = b2[lane];
    const u64 bias2 = pk2(b2l, b2l);
    const float s1 = g_scale1[lane], f1 = g_shift1[lane];
    const u64 sc2 = pk2(s1, s1), sf2 = pk2(f1, f1);

    u64 ssum = 0ull, ssq = 0ull;
    const int warpId = (blockIdx.x * blockDim.x + threadIdx.x) >> 5;
    const int nwarps = (gridDim.x * blockDim.x) >> 5;

    for (int p = warpId; p < NPP; p += nwarps) {
        float e0 = (lane < EPG) ? ew[(size_t)p * (2 * EPG) + lane] : 0.f;
        float e1 = (lane < EPG) ? ew[(size_t)p * (2 * EPG) + EPG + lane] : 0.f;
        float dv0[6], dv1[6];
        dinv6(e0, lane, dv0); dinv6(e1, lane, dv1);
        buildA2(e0, e1, lane, dv0, dv1, sA2);

        const u64* hp = g_h1 + (size_t)p * (NPG * HD) + lane;
        u64 h2[NPG];
        #pragma unroll
        for (int t = 0; t < NPG; t++) h2[t] = relu2_(fma2_(hp[t * HD], sc2, sf2));
        __syncwarp();

        // ha2[t] (this lane's feature) = sum_s A2[t][s] * h2[s]
        #pragma unroll
        for (int t = 0; t < NPG; t++) {
            u64 v = 0ull;
            const float4* arow = (const float4*)(sA2 + t * 8);
            #pragma unroll
            for (int sh = 0; sh < 3; sh++) {
                float4 a4 = arow[sh];
                v = fma2_(pk2(a4.x, a4.y), h2[2 * sh], v);
                v = fma2_(pk2(a4.z, a4.w), h2[2 * sh + 1], v);
            }
            sha2[t * HD + lane] = v;
        }
        __syncwarp();

        u64* outp = g_h2 + (size_t)p * (NPG * HD) + lane;
        #pragma unroll
        for (int t = 0; t < NPG; t++) {
            u64 acc = bias2;
            const float4* rowp = (const float4*)(sha2 + t * HD);
            #pragma unroll
            for (int cc = 0; cc < 16; cc++) {
                float4 v4 = rowp[cc];
                acc = fma2_(pk2(v4.x, v4.y), wp[2 * cc], acc);
                acc = fma2_(pk2(v4.z, v4.w), wp[2 * cc + 1], acc);
            }
            outp[t * HD] = acc;
            ssum = add2_(ssum, acc);
            ssq  = fma2_(acc, acc, ssq);
        }
        __syncwarp();
    }

    float sa, sb, qa, qb;
    up2(ssum, sa, sb); up2(ssq, qa, qb);
    sred[w][lane] = sa + sb; sred[w][32 + lane] = qa + qb;
    __syncthreads();
    if (threadIdx.x < 64) {
        float tot = 0.f;
        #pragma unroll
        for (int i = 0; i < 8; i++) tot += sred[i][threadIdx.x];
        if (threadIdx.x < 32) atomicAdd(&g_sum2[threadIdx.x], tot);
        else                  atomicAdd(&g_sq2[threadIdx.x - 32], tot);
    }
}

// ---------------- K5: bn2+relu, mean-pool, readout, sigmoid (2 graphs/warp) ----------------
__global__ void __launch_bounds__(256) k5(const float* __restrict__ gf,
                                          const float* __restrict__ Wo,
                                          const float* __restrict__ bo,
                                          const float* __restrict__ Wb,
                                          const float* __restrict__ bb,
                                          float* __restrict__ out) {
    const int lane = threadIdx.x & 31;
    const int p = (blockIdx.x * blockDim.x + threadIdx.x) >> 5;
    if (p >= NPP) return;

    const float s2 = g_scale2[lane], f2 = g_shift2[lane];
    const u64 sc2 = pk2(s2, s2), sf2 = pk2(f2, f2);
    const float wol = Wo[lane], wbl = Wb[lane];
    const float wog = (lane < GD) ? Wo[HD + lane] : 0.f;
    const float wbg = (lane < GD) ? Wb[HD + lane] : 0.f;

    const u64* hp = g_h2 + (size_t)p * (NPG * HD) + lane;
    u64 pool = 0ull;
    #pragma unroll
    for (int t = 0; t < NPG; t++) pool = add2_(pool, relu2_(fma2_(hp[t * HD], sc2, sf2)));
    float p0, p1; up2(pool, p0, p1);
    p0 *= (1.0f / 6.0f); p1 *= (1.0f / 6.0f);

    float gv0 = (lane < GD) ? gf[(size_t)p * (2 * GD) + lane] : 0.f;
    float gv1 = (lane < GD) ? gf[(size_t)p * (2 * GD) + GD + lane] : 0.f;

    float zo0 = fmaf(p0, wol, gv0 * wog);
    float zo1 = fmaf(p1, wol, gv1 * wog);
    float zb0 = fmaf(p0, wbl, gv0 * wbg);
    float zb1 = fmaf(p1, wbl, gv1 * wbg);
    #pragma unroll
    for (int o = 16; o; o >>= 1) {
        zo0 += __shfl_xor_sync(0xffffffffu, zo0, o);
        zo1 += __shfl_xor_sync(0xffffffffu, zo1, o);
        zb0 += __shfl_xor_sync(0xffffffffu, zb0, o);
        zb1 += __shfl_xor_sync(0xffffffffu, zb1, o);
    }
    if (lane == 0) {
        float bov = bo[0], bbv = bb[0];
        int g0 = 2 * p;
        float2 ro = make_float2(1.0f / (1.0f + __expf(-(zo0 + bov))),
                                1.0f / (1.0f + __expf(-(zo1 + bov))));
        float2 rb = make_float2(1.0f / (1.0f + __expf(-(zb0 + bbv))),
                                1.0f / (1.0f + __expf(-(zb1 + bbv))));
        *(float2*)(out + g0)      = ro;
        *(float2*)(out + NG + g0) = rb;
    }
}

// ---------------- launch ----------------
extern "C" void kernel_launch(void* const* d_in, const int* in_sizes, int n_in,
                              void* d_out, int out_size) {
    const float* x   = (const float*)d_in[0];
    const float* ew  = (const float*)d_in[2];
    const float* gf  = (const float*)d_in[4];
    const float* W1  = (const float*)d_in[5];
    const float* b1  = (const float*)d_in[6];
    const float* g1  = (const float*)d_in[7];
    const float* be1 = (const float*)d_in[8];
    const float* W2  = (const float*)d_in[9];
    const float* b2  = (const float*)d_in[10];
    const float* g2  = (const float*)d_in[11];
    const float* be2 = (const float*)d_in[12];
    const float* Wo  = (const float*)d_in[13];
    const float* bo  = (const float*)d_in[14];
    const float* Wb  = (const float*)d_in[15];
    const float* bb  = (const float*)d_in[16];
    float* out = (float*)d_out;

    k_zero_stats<<<1, 64>>>();
    k1<<<2048, 256>>>(x, ew, W1, b1);
    k_bn<<<1, 32>>>(g1, be1, 0);
    k3<<<2048, 256>>>(ew, W2, b2);
    k_bn<<<1, 32>>>(g2, be2, 1);
    k5<<<NPP / 8, 256>>>(gf, Wo, bo, Wb, bb, out);
}